// round 15
// baseline (speedup 1.0000x reference)
#include <cuda_runtime.h>
#include <cuda_bf16.h>

// Problem: cummax along axis=2 of x[B=8, Tt=128, Ts=128, C=512] fp32.
// out[b,t,j,c] = max_{j'<=j} x[b,t,j',c]
//
// FINAL (R12 champion, re-confirmed): 1024 CTAs x 128 threads, one CTA per
// (b,t) row, plain LDG.128/STG.128, j-loop fully unrolled. 14 rounds of
// experiments (occupancy 20-80%, widths 8/16/32B, cache hints, cp.async,
// bulk ld/st, phase batching) all plateau at ~75-77% DRAM / ~6.0 TB/s:
// the intrinsic mixed-R/W DRAM ceiling for this 50/50 streaming pattern.
// This config holds the best bench (90.7us) and ties best DRAM%.
//
// Hard-won rules encoded here:
//  - NO cache-op intrinsics (.cs/.lu): 3x regressions, they break ptxas
//    load batching (regs drop, MLP collapses).
//  - NO smem staging / bulk copies / syncthreads: per-lane scoreboarded
//    LDG beats every synchronized pipeline for the load stream.
//  - 1024-CTA grid: 7-vs-6 CTAs/SM balance (vs 4-vs-3 at 512) -> +1.5%.
//  - Full unroll: whole dependence graph visible to ptxas, zero branches.

static __device__ __forceinline__ float4 f4max(float4 a, float4 b) {
    float4 r;
    r.x = fmaxf(a.x, b.x);
    r.y = fmaxf(a.y, b.y);
    r.z = fmaxf(a.z, b.z);
    r.w = fmaxf(a.w, b.w);
    return r;
}

// One CTA per (b,t) row: 128 threads cover the 128 float4 channel groups.
// Each thread walks j = 0..127 (stride 2KB) with a register running max.
__global__ void __launch_bounds__(128) cummax_kernel(
    const float4* __restrict__ in, float4* __restrict__ out)
{
    constexpr int TS = 128;
    constexpr int C4 = 128;               // 512 channels / 4
    const int bt = blockIdx.x;            // (b,t) row, 0..1023
    const int c4 = threadIdx.x;           // float4 within C, 0..127

    const float4* __restrict__ p = in  + (size_t)bt * TS * C4 + c4;
    float4* __restrict__       q = out + (size_t)bt * TS * C4 + c4;

    float4 m = p[0];
    q[0] = m;

    #pragma unroll
    for (int j = 1; j < TS; ++j) {
        float4 v = p[(size_t)j * C4];
        m = f4max(m, v);
        q[(size_t)j * C4] = m;
    }
}

extern "C" void kernel_launch(void* const* d_in, const int* in_sizes, int n_in,
                              void* d_out, int out_size)
{
    const float4* x = (const float4*)d_in[0];
    float4* y = (float4*)d_out;

    // 1024 CTAs = B*Tt rows; 128 threads = C/4 float4 columns per row.
    cummax_kernel<<<1024, 128>>>(x, y);
}

// round 16
// speedup vs baseline: 1.0102x; 1.0102x over previous
#include <cuda_runtime.h>
#include <cuda_bf16.h>

// Problem: cummax along axis=2 of x[B=8, Tt=128, Ts=128, C=512] fp32.
// out[b,t,j,c] = max_{j'<=j} x[b,t,j',c]
//
// FINAL FORM (R7 body, clean unroll 16): 1024 CTAs x 128 threads, one CTA
// per (b,t) row, plain LDG.128/STG.128 rolled loop. 15 rounds established:
//  - ~75-77% DRAM / ~6.0 TB/s is the mixed-R/W ceiling for this 50/50
//    streaming pattern (occupancy, width, hints, cp.async, bulk ld/st,
//    phase batching all plateau or regress).
//  - Rolled unroll-8 body (R7) holds the best ncu reading (76.7%/80.4us):
//    ~1KB body stays L0-I$-resident vs 10KB full unroll (75.5% x3).
//  - Unroll 16 is the only clean-untested depth (R3's test was confounded
//    with __ldcs): 2x ptxas scheduling window, ~2.5KB body still in L0.
// Excluded by hard evidence: cache-op intrinsics (3x regressions, break
// ptxas load batching), smem/sync staging (2x), bulk copies (2x).

static __device__ __forceinline__ float4 f4max(float4 a, float4 b) {
    float4 r;
    r.x = fmaxf(a.x, b.x);
    r.y = fmaxf(a.y, b.y);
    r.z = fmaxf(a.z, b.z);
    r.w = fmaxf(a.w, b.w);
    return r;
}

// One CTA per (b,t) row: 128 threads cover the 128 float4 channel groups.
// Each thread walks j = 0..127 (stride 2KB) with a register running max.
__global__ void __launch_bounds__(128) cummax_kernel(
    const float4* __restrict__ in, float4* __restrict__ out)
{
    constexpr int TS = 128;
    constexpr int C4 = 128;               // 512 channels / 4
    const int bt = blockIdx.x;            // (b,t) row, 0..1023
    const int c4 = threadIdx.x;           // float4 within C, 0..127

    const float4* __restrict__ p = in  + (size_t)bt * TS * C4 + c4;
    float4* __restrict__       q = out + (size_t)bt * TS * C4 + c4;

    float4 m = p[0];
    q[0] = m;

    #pragma unroll 16
    for (int j = 1; j < TS; ++j) {
        float4 v = p[(size_t)j * C4];
        m = f4max(m, v);
        q[(size_t)j * C4] = m;
    }
}

extern "C" void kernel_launch(void* const* d_in, const int* in_sizes, int n_in,
                              void* d_out, int out_size)
{
    const float4* x = (const float4*)d_in[0];
    float4* y = (float4*)d_out;

    // 1024 CTAs = B*Tt rows; 128 threads = C/4 float4 columns per row.
    cummax_kernel<<<1024, 128>>>(x, y);
}

// round 17
// speedup vs baseline: 1.0180x; 1.0078x over previous
#include <cuda_runtime.h>
#include <cuda_bf16.h>

// Problem: cummax along axis=2 of x[B=8, Tt=128, Ts=128, C=512] fp32.
// out[b,t,j,c] = max_{j'<=j} x[b,t,j',c]
//
// FINAL (R7 configuration — best hardware measurement of the session:
// 76.7% DRAM / 80.4us ncu). 1024 CTAs x 128 threads, one CTA per (b,t)
// row, plain LDG.128/STG.128, rolled loop at unroll 8 (~1KB body, stays
// L0-I$-resident; deeper unrolls measured 75.5-75.7%).
//
// 16-round record behind this shape — all alternatives plateau or regress:
//  - cache-op intrinsics (.cs/.lu): 3x regressions (-15..-17%), they break
//    ptxas load batching (regs drop, MLP collapses).
//  - smem/sync staging, cp.async, bulk ld/st: sync on the load path or
//    single-thread issue starves the read stream (-8..-10%).
//  - occupancy 20%/80%, widths 8B/32B: worse than 40% occ + 16B.
//  - 1024-CTA grid: 7-vs-6 CTAs/SM balance beats 512's 4-vs-3 (+1.5%).
// Remaining ~24% DRAM idle = memory-controller efficiency on a 50/50
// interleaved R/W stream; not SM-controllable. This is the roofline.

static __device__ __forceinline__ float4 f4max(float4 a, float4 b) {
    float4 r;
    r.x = fmaxf(a.x, b.x);
    r.y = fmaxf(a.y, b.y);
    r.z = fmaxf(a.z, b.z);
    r.w = fmaxf(a.w, b.w);
    return r;
}

// One CTA per (b,t) row: 128 threads cover the 128 float4 channel groups.
// Each thread walks j = 0..127 (stride 2KB) with a register running max.
__global__ void __launch_bounds__(128) cummax_kernel(
    const float4* __restrict__ in, float4* __restrict__ out)
{
    constexpr int TS = 128;
    constexpr int C4 = 128;               // 512 channels / 4
    const int bt = blockIdx.x;            // (b,t) row, 0..1023
    const int c4 = threadIdx.x;           // float4 within C, 0..127

    const float4* __restrict__ p = in  + (size_t)bt * TS * C4 + c4;
    float4* __restrict__       q = out + (size_t)bt * TS * C4 + c4;

    float4 m = p[0];
    q[0] = m;

    #pragma unroll 8
    for (int j = 1; j < TS; ++j) {
        float4 v = p[(size_t)j * C4];
        m = f4max(m, v);
        q[(size_t)j * C4] = m;
    }
}

extern "C" void kernel_launch(void* const* d_in, const int* in_sizes, int n_in,
                              void* d_out, int out_size)
{
    const float4* x = (const float4*)d_in[0];
    float4* y = (float4*)d_out;

    // 1024 CTAs = B*Tt rows; 128 threads = C/4 float4 columns per row.
    cummax_kernel<<<1024, 128>>>(x, y);
}